// round 11
// baseline (speedup 1.0000x reference)
#include <cuda_runtime.h>

#define N_NEURONS 131072
#define NSTATES   32
#define CDIM      16
#define NBATCH    4
#define X_ELEMS   (NBATCH * N_NEURONS * NSTATES)   // 16777216
#define S_ELEMS   (N_NEURONS * NSTATES)            // 4194304

typedef unsigned long long u64;

// ---------------- constant-memory weights (LDCU port, not LSU/L1) ----------------
__constant__ u64   cWenc2[CDIM * NSTATES / 2];   // [j][s-pair]: 16 u64 per row
__constant__ u64   cWdec2[NSTATES * CDIM / 2];   // [s][j-pair]: 8 u64 per row
__constant__ float cbenc[CDIM];
__constant__ float cbdec[NSTATES];

// ---------------- f32x2 packed helpers ----------------
__device__ __forceinline__ u64 pack2(float a, float b) {
    u64 r; asm("mov.b64 %0, {%1, %2};" : "=l"(r) : "f"(a), "f"(b)); return r;
}
__device__ __forceinline__ float2 unpack2(u64 v) {
    float2 f; asm("mov.b64 {%0, %1}, %2;" : "=f"(f.x), "=f"(f.y) : "l"(v)); return f;
}
__device__ __forceinline__ u64 fma2(u64 a, u64 b, u64 c) {
    u64 d; asm("fma.rn.f32x2 %0, %1, %2, %3;" : "=l"(d) : "l"(a), "l"(b), "l"(c)); return d;
}
__device__ __forceinline__ u64 mul2(u64 a, u64 b) {
    u64 d; asm("mul.rn.f32x2 %0, %1, %2;" : "=l"(d) : "l"(a), "l"(b)); return d;
}

__device__ __forceinline__ float mufu_tanh(float x) {
    float t; asm("tanh.approx.f32 %0, %1;" : "=f"(t) : "f"(x)); return t;
}

// =================== tanh kernel: pure MUFU tanh^4, 32 elems/thread ===================
#define TTPB 256
#define TANH_GRID (X_ELEMS / 32 / TTPB)   // 2048 blocks

__device__ __forceinline__ float tanh4(float x) {
    float t = mufu_tanh(x);
    t = mufu_tanh(t);
    t = mufu_tanh(t);
    t = mufu_tanh(t);
    return t;
}

__global__ void __launch_bounds__(TTPB)
tanh_kernel(const float4* __restrict__ xin, float4* __restrict__ xout)
{
    const int base = blockIdx.x * (TTPB * 8) + threadIdx.x;
    #pragma unroll
    for (int half = 0; half < 2; half++) {
        float4 v[4];
        #pragma unroll
        for (int k = 0; k < 4; k++) v[k] = xin[base + (half * 4 + k) * TTPB];
        #pragma unroll
        for (int k = 0; k < 4; k++) {
            v[k].x = tanh4(v[k].x);
            v[k].y = tanh4(v[k].y);
            v[k].z = tanh4(v[k].z);
            v[k].w = tanh4(v[k].w);
        }
        #pragma unroll
        for (int k = 0; k < 4; k++) xout[base + (half * 4 + k) * TTPB] = v[k];
    }
}

// =================== states kernel: 2 neurons/thread, const weights, no smem ===================
#define STPB 32
#define NPT  2

// compare-exchange, descending (hi to lower index)
#define CE(arr, i, j) { float _hi = fmaxf(arr[i], arr[j]); \
                        float _lo = fminf(arr[i], arr[j]); \
                        arr[i] = _hi; arr[j] = _lo; }

// descending Batcher sort-8 in place
#define SORT8(v) { \
    CE(v,0,1) CE(v,2,3) CE(v,4,5) CE(v,6,7) \
    CE(v,0,2) CE(v,1,3) CE(v,4,6) CE(v,5,7) \
    CE(v,1,2) CE(v,5,6) \
    CE(v,0,4) CE(v,1,5) CE(v,2,6) CE(v,3,7) \
    CE(v,2,4) CE(v,3,5) \
    CE(v,1,2) CE(v,3,4) CE(v,5,6) }

// bitonic clean of a bitonic-descending 8-seq into sorted desc
#define BSORT8(z) { \
    CE(z,0,4) CE(z,1,5) CE(z,2,6) CE(z,3,7) \
    CE(z,0,2) CE(z,1,3) CE(z,4,6) CE(z,5,7) \
    CE(z,0,1) CE(z,2,3) CE(z,4,5) CE(z,6,7) }

__global__ void __launch_bounds__(STPB, 16)   // 128-reg cap; no smem; 2048 blocks ~1 wave
states_kernel(const float* __restrict__ ns, float* __restrict__ sout)
{
    const int n0 = blockIdx.x * (STPB * NPT) + threadIdx.x;   // neurons n0 and n0+STPB

    // persistent per-thread state: packed current states + compressed encoder dots
    u64 st2[NPT][NSTATES / 2];     // 64 regs
    u64 dotE2[NPT][CDIM / 2];      // 32 regs
    #pragma unroll
    for (int p = 0; p < NPT; p++) {
        const u64* src = reinterpret_cast<const u64*>(ns)
                       + (size_t)(n0 + p * STPB) * (NSTATES / 2);
        #pragma unroll
        for (int i = 0; i < NSTATES / 2; i++) {
            float2 f = unpack2(src[i]);
            // layer-0 sparsity mask (no-op later: survivors are 0 or >= 0.05)
            f.x = (fabsf(f.x) >= 0.01f) ? f.x : 0.0f;
            f.y = (fabsf(f.y) >= 0.01f) ? f.y : 0.0f;
            st2[p][i] = pack2(f.x, f.y);
        }
        #pragma unroll
        for (int i = 0; i < CDIM / 2; i++) dotE2[p][i] = 0ull;
    }

    const u64 K07 = pack2(0.7f, 0.7f);

    #pragma unroll 1
    for (int L = 0; L < 4; L++) {
        // 0.9 decay folded into the recency normalizer
        const float wscl = (L == 0) ? 0.9f
                         : (L == 1) ? (0.9f / 1.7f)
                         : (L == 2) ? (0.9f / 2.19f)
                         :            (0.9f / 2.533f);

        // ---- encoder: fresh = Wenc @ st ; dotE = 0.7*dotE + fresh ;
        //      h = relu(wscl*dotE + benc)  (const weights feed both neurons) ----
        u64 ph[NPT][CDIM / 2];
        #pragma unroll 2
        for (int j2 = 0; j2 < CDIM / 2; j2++) {
            float fr[NPT][2];
            #pragma unroll
            for (int q = 0; q < 2; q++) {
                const int j = 2 * j2 + q;
                u64 a0 = 0ull, a1 = 0ull;
                #pragma unroll
                for (int k = 0; k < 16; k++) {
                    const u64 wv = cWenc2[j * 16 + k];
                    a0 = fma2(st2[0][k], wv, a0);
                    a1 = fma2(st2[1][k], wv, a1);
                }
                float2 f0 = unpack2(a0);
                float2 f1 = unpack2(a1);
                fr[0][q] = f0.x + f0.y;
                fr[1][q] = f1.x + f1.y;
            }
            const float b0 = cbenc[2*j2+0];
            const float b1 = cbenc[2*j2+1];
            #pragma unroll
            for (int p = 0; p < NPT; p++) {
                dotE2[p][j2] = fma2(dotE2[p][j2], K07, pack2(fr[p][0], fr[p][1]));
                float2 d = unpack2(dotE2[p][j2]);
                float h0 = fmaxf(fmaf(d.x, wscl, b0), 0.0f);
                float h1 = fmaxf(fmaf(d.y, wscl, b1), 0.0f);
                ph[p][j2] = pack2(h0, h1);
            }
        }

        // ---- decoder + importance threshold (const weights), writes st2 ----
        #pragma unroll 4
        for (int i = 0; i < NSTATES / 2; i++) {
            float o[NPT][2];
            #pragma unroll
            for (int q = 0; q < 2; q++) {
                const int s = 2 * i + q;
                u64 a0 = 0ull, a1 = 0ull;
                #pragma unroll
                for (int k = 0; k < 8; k++) {
                    const u64 wv = cWdec2[s * 8 + k];
                    a0 = fma2(ph[0][k], wv, a0);
                    a1 = fma2(ph[1][k], wv, a1);
                }
                const float b = cbdec[s];
                float2 f0 = unpack2(a0);
                float2 f1 = unpack2(a1);
                float v0 = f0.x + f0.y + b;
                float v1 = f1.x + f1.y + b;
                o[0][q] = (fabsf(v0) >= 0.05f) ? v0 : 0.0f;
                o[1][q] = (fabsf(v1) >= 0.05f) ? v1 : 0.0f;
            }
            st2[0][i] = pack2(o[0][0], o[0][1]);
            st2[1][i] = pack2(o[1][0], o[1][1]);
        }

        // ---- exact 8th-largest of |st| per neuron: streaming sort8 + bitonic merges ----
        #pragma unroll
        for (int p = 0; p < NPT; p++) {
            float m[8], g[8];
            #pragma unroll
            for (int i = 0; i < 4; i++) {
                float2 f = unpack2(st2[p][i] & 0x7FFFFFFF7FFFFFFFull);
                m[2*i] = f.x; m[2*i+1] = f.y;
            }
            SORT8(m)
            #pragma unroll
            for (int gr = 1; gr < 4; gr++) {
                #pragma unroll
                for (int i = 0; i < 4; i++) {
                    float2 f = unpack2(st2[p][gr*4 + i] & 0x7FFFFFFF7FFFFFFFull);
                    g[2*i] = f.x; g[2*i+1] = f.y;
                }
                SORT8(g)
                #pragma unroll
                for (int i = 0; i < 8; i++) m[i] = fmaxf(m[i], g[7 - i]);
                BSORT8(m)
            }
            const float kth = m[7];
            #pragma unroll
            for (int i = 0; i < NSTATES / 2; i++) {
                float2 f = unpack2(st2[p][i]);
                f.x = (fabsf(f.x) >= kth) ? f.x : 0.0f;
                f.y = (fabsf(f.y) >= kth) ? f.y : 0.0f;
                st2[p][i] = pack2(f.x, f.y);
            }
        }
    }

    #pragma unroll
    for (int p = 0; p < NPT; p++) {
        ulonglong2* dst = reinterpret_cast<ulonglong2*>(sout)
                        + (size_t)(n0 + p * STPB) * (NSTATES / 4);
        #pragma unroll
        for (int i = 0; i < NSTATES / 4; i++) {
            ulonglong2 v;
            v.x = st2[p][2*i+0];
            v.y = st2[p][2*i+1];
            dst[i] = v;
        }
    }
}

extern "C" void kernel_launch(void* const* d_in, const int* in_sizes, int n_in,
                              void* d_out, int out_size) {
    const float* x    = (const float*)d_in[0];
    const float* ns   = (const float*)d_in[1];
    const float* Wenc = (const float*)d_in[2];
    const float* benc = (const float*)d_in[3];
    const float* Wdec = (const float*)d_in[4];
    const float* bdec = (const float*)d_in[5];

    float* out  = (float*)d_out;
    float* xout = nullptr;
    float* sout = nullptr;
    if (out_size >= X_ELEMS + S_ELEMS) { xout = out; sout = out + X_ELEMS; }
    else if (out_size == S_ELEMS)      { sout = out; }
    else                               { xout = out; }

    if (xout)
        tanh_kernel<<<TANH_GRID, TTPB>>>(reinterpret_cast<const float4*>(x),
                                         reinterpret_cast<float4*>(xout));
    if (sout) {
        // async D2D copies into __constant__ (graph-capturable memcpy nodes)
        cudaMemcpyToSymbolAsync(cWenc2, Wenc, CDIM * NSTATES * sizeof(float), 0,
                                cudaMemcpyDeviceToDevice);
        cudaMemcpyToSymbolAsync(cWdec2, Wdec, NSTATES * CDIM * sizeof(float), 0,
                                cudaMemcpyDeviceToDevice);
        cudaMemcpyToSymbolAsync(cbenc, benc, CDIM * sizeof(float), 0,
                                cudaMemcpyDeviceToDevice);
        cudaMemcpyToSymbolAsync(cbdec, bdec, NSTATES * sizeof(float), 0,
                                cudaMemcpyDeviceToDevice);
        states_kernel<<<N_NEURONS / (STPB * NPT), STPB>>>(ns, sout);
    }
}

// round 12
// speedup vs baseline: 1.1311x; 1.1311x over previous
#include <cuda_runtime.h>

#define N_NEURONS 131072
#define NSTATES   32
#define CDIM      16
#define NBATCH    4
#define X_ELEMS   (NBATCH * N_NEURONS * NSTATES)   // 16777216
#define S_ELEMS   (N_NEURONS * NSTATES)            // 4194304

typedef unsigned long long u64;

// ---------------- constant-memory weights (LDCU port, not LSU/L1) ----------------
__constant__ u64 cWenc2[CDIM * NSTATES / 2];   // [j][s-pair]: 16 u64 per row
__constant__ u64 cWdec2[NSTATES * CDIM / 2];   // [s][j-pair]: 8 u64 per row

// ---------------- fork/join resources, created at static init ----------------
struct ForkRes {
    cudaStream_t s2 = nullptr;
    cudaEvent_t  evFork = nullptr, evJoin = nullptr;
    bool ok = false;
    ForkRes() {
        if (cudaStreamCreateWithFlags(&s2, cudaStreamNonBlocking) != cudaSuccess) return;
        if (cudaEventCreateWithFlags(&evFork, cudaEventDisableTiming) != cudaSuccess) return;
        if (cudaEventCreateWithFlags(&evJoin, cudaEventDisableTiming) != cudaSuccess) return;
        ok = true;
    }
};
static ForkRes g_fork;

// ---------------- f32x2 packed helpers ----------------
__device__ __forceinline__ u64 pack2(float a, float b) {
    u64 r; asm("mov.b64 %0, {%1, %2};" : "=l"(r) : "f"(a), "f"(b)); return r;
}
__device__ __forceinline__ float2 unpack2(u64 v) {
    float2 f; asm("mov.b64 {%0, %1}, %2;" : "=f"(f.x), "=f"(f.y) : "l"(v)); return f;
}
__device__ __forceinline__ u64 fma2(u64 a, u64 b, u64 c) {
    u64 d; asm("fma.rn.f32x2 %0, %1, %2, %3;" : "=l"(d) : "l"(a), "l"(b), "l"(c)); return d;
}
__device__ __forceinline__ u64 mul2(u64 a, u64 b) {
    u64 d; asm("mul.rn.f32x2 %0, %1, %2;" : "=l"(d) : "l"(a), "l"(b)); return d;
}

// ---------------- tanh pieces (R10 hybrid, measured 23us / rel_err 1e-4) ----------------
__device__ __forceinline__ u64 poly2(u64 x2, const u64* __restrict__ C) {
    u64 t2 = mul2(x2, x2);
    u64 p  = fma2(t2, C[0], C[1]);
    p = fma2(t2, p, C[2]);
    p = fma2(t2, p, C[3]);
    p = fma2(t2, p, C[4]);
    p = fma2(t2, p, C[5]);
    p = fma2(t2, p, C[6]);
    p = fma2(t2, p, C[7]);
    return mul2(p, x2);
}

__device__ __forceinline__ void make_coeffs(u64* C) {
    const float c[8] = { -0.001455834387f,  0.003592128037f, -0.008863235530f,
                          0.021869488537f, -0.053968253968f,  0.133333333333f,
                         -0.333333333333f,  1.0f };
    #pragma unroll
    for (int i = 0; i < 8; i++) C[i] = pack2(c[i], c[i]);
}

__device__ __forceinline__ float mufu_tanh(float x) {
    float t; asm("tanh.approx.f32 %0, %1;" : "=f"(t) : "f"(x)); return t;
}

__device__ __forceinline__ void tanh_s1_pair(float& a, float& b) {
    const float xa = a, xb = b;
    float ta = mufu_tanh(xa);
    float tb = mufu_tanh(xb);
    u64 x2 = pack2(xa, xb);
    u64 t2 = mul2(x2, x2);
    u64 p  = fma2(t2, pack2(-0.333333333f, -0.333333333f), pack2(1.0f, 1.0f));
    float2 pp = unpack2(mul2(p, x2));
    a = (fabsf(xa) >= 0.125f) ? ta : pp.x;
    b = (fabsf(xb) >= 0.125f) ? tb : pp.y;
}

__device__ __forceinline__ void tanh_s2_pair(float& a, float& b) {
    const float ya = a, yb = b;
    float2 s = unpack2(mul2(pack2(ya, yb), pack2(2.8853900817779268f, 2.8853900817779268f)));
    float ea, eb;
    asm("ex2.approx.ftz.f32 %0, %1;" : "=f"(ea) : "f"(s.x));
    asm("ex2.approx.ftz.f32 %0, %1;" : "=f"(eb) : "f"(s.y));
    float na = ea - 1.0f, da = ea + 1.0f;
    float nb = eb - 1.0f, db = eb + 1.0f;
    float ra, rb;
    asm("rcp.approx.ftz.f32 %0, %1;" : "=f"(ra) : "f"(da));
    asm("rcp.approx.ftz.f32 %0, %1;" : "=f"(rb) : "f"(db));
    float ta = na * ra;
    float tb = nb * rb;
    a = (fabsf(ya) >= 0.01f) ? ta : ya;
    b = (fabsf(yb) >= 0.01f) ? tb : yb;
}

__device__ __forceinline__ void tanh4_pair(float& a, float& b, const u64* __restrict__ C) {
    tanh_s1_pair(a, b);
    tanh_s2_pair(a, b);
    float2 f = unpack2(poly2(pack2(a, b), C)); a = f.x; b = f.y;
    f = unpack2(poly2(pack2(a, b), C));        a = f.x; b = f.y;
}

// =================== tanh kernel: 32 elems/thread ===================
#define TTPB 256
#define TANH_GRID (X_ELEMS / 32 / TTPB)   // 2048 blocks

__global__ void __launch_bounds__(TTPB)
tanh_kernel(const float4* __restrict__ xin, float4* __restrict__ xout)
{
    u64 C[8];
    make_coeffs(C);

    const int base = blockIdx.x * (TTPB * 8) + threadIdx.x;
    #pragma unroll
    for (int half = 0; half < 2; half++) {
        float4 v[4];
        #pragma unroll
        for (int k = 0; k < 4; k++) v[k] = xin[base + (half * 4 + k) * TTPB];
        #pragma unroll
        for (int k = 0; k < 4; k++) {
            tanh4_pair(v[k].x, v[k].y, C);
            tanh4_pair(v[k].z, v[k].w, C);
        }
        #pragma unroll
        for (int k = 0; k < 4; k++) xout[base + (half * 4 + k) * TTPB] = v[k];
    }
}

// =================== states kernel: 1 neuron/thread, const weights, no smem ===================
#define STPB 32

// compare-exchange, descending (hi to lower index)
#define CE(arr, i, j) { float _hi = fmaxf(arr[i], arr[j]); \
                        float _lo = fminf(arr[i], arr[j]); \
                        arr[i] = _hi; arr[j] = _lo; }

// descending Batcher sort-8 in place
#define SORT8(v) { \
    CE(v,0,1) CE(v,2,3) CE(v,4,5) CE(v,6,7) \
    CE(v,0,2) CE(v,1,3) CE(v,4,6) CE(v,5,7) \
    CE(v,1,2) CE(v,5,6) \
    CE(v,0,4) CE(v,1,5) CE(v,2,6) CE(v,3,7) \
    CE(v,2,4) CE(v,3,5) \
    CE(v,1,2) CE(v,3,4) CE(v,5,6) }

// bitonic clean of a bitonic-descending 8-seq into sorted desc
#define BSORT8(z) { \
    CE(z,0,4) CE(z,1,5) CE(z,2,6) CE(z,3,7) \
    CE(z,0,2) CE(z,1,3) CE(z,4,6) CE(z,5,7) \
    CE(z,0,1) CE(z,2,3) CE(z,4,5) CE(z,6,7) }

__global__ void __launch_bounds__(STPB, 24)   // 85-reg cap; up to 24 warps/SM
states_kernel(const float* __restrict__ ns,
              const float* __restrict__ benc,
              const float* __restrict__ bdec,
              float* __restrict__ sout)
{
    const int n = blockIdx.x * STPB + threadIdx.x;

    // persistent per-thread state: packed current states + compressed encoder dots
    u64 st2[NSTATES / 2];     // 32 regs
    u64 dotE2[CDIM / 2];      // 16 regs
    {
        const u64* src = reinterpret_cast<const u64*>(ns) + (size_t)n * (NSTATES / 2);
        #pragma unroll
        for (int i = 0; i < NSTATES / 2; i++) {
            float2 f = unpack2(src[i]);
            // layer-0 sparsity mask (no-op later: survivors are 0 or >= 0.05)
            f.x = (fabsf(f.x) >= 0.01f) ? f.x : 0.0f;
            f.y = (fabsf(f.y) >= 0.01f) ? f.y : 0.0f;
            st2[i] = pack2(f.x, f.y);
        }
        #pragma unroll
        for (int i = 0; i < CDIM / 2; i++) dotE2[i] = 0ull;
    }

    const u64 K07 = pack2(0.7f, 0.7f);

    #pragma unroll 1
    for (int L = 0; L < 4; L++) {
        // 0.9 decay folded into the recency normalizer
        const float wscl = (L == 0) ? 0.9f
                         : (L == 1) ? (0.9f / 1.7f)
                         : (L == 2) ? (0.9f / 2.19f)
                         :            (0.9f / 2.533f);

        // ---- encoder: fresh = Wenc @ st ; dotE = 0.7*dotE + fresh ;
        //      h = relu(wscl*dotE + benc) ----
        u64 ph[CDIM / 2];
        #pragma unroll 2
        for (int j2 = 0; j2 < CDIM / 2; j2++) {
            float fr[2];
            #pragma unroll
            for (int q = 0; q < 2; q++) {
                const int j = 2 * j2 + q;
                u64 a = 0ull;
                #pragma unroll
                for (int k = 0; k < 16; k++)
                    a = fma2(st2[k], cWenc2[j * 16 + k], a);
                float2 f = unpack2(a);
                fr[q] = f.x + f.y;
            }
            dotE2[j2] = fma2(dotE2[j2], K07, pack2(fr[0], fr[1]));
            float2 d = unpack2(dotE2[j2]);
            float h0 = fmaxf(fmaf(d.x, wscl, __ldg(&benc[2*j2+0])), 0.0f);
            float h1 = fmaxf(fmaf(d.y, wscl, __ldg(&benc[2*j2+1])), 0.0f);
            ph[j2] = pack2(h0, h1);
        }

        // ---- decoder: raw rec into st2 (importance mask fused into top-k below) ----
        #pragma unroll 4
        for (int i = 0; i < NSTATES / 2; i++) {
            float o[2];
            #pragma unroll
            for (int q = 0; q < 2; q++) {
                const int s = 2 * i + q;
                u64 a = 0ull;
                #pragma unroll
                for (int k = 0; k < 8; k++)
                    a = fma2(ph[k], cWdec2[s * 8 + k], a);
                float2 f = unpack2(a);
                o[q] = f.x + f.y + __ldg(&bdec[s]);
            }
            st2[i] = pack2(o[0], o[1]);
        }

        // ---- T = max(8th-largest |rec|, 0.05): fuses importance + top-k masks ----
        float m[8], g[8];
        #pragma unroll
        for (int i = 0; i < 4; i++) {
            float2 f = unpack2(st2[i] & 0x7FFFFFFF7FFFFFFFull);
            m[2*i] = f.x; m[2*i+1] = f.y;
        }
        SORT8(m)
        #pragma unroll
        for (int gr = 1; gr < 4; gr++) {
            #pragma unroll
            for (int i = 0; i < 4; i++) {
                float2 f = unpack2(st2[gr*4 + i] & 0x7FFFFFFF7FFFFFFFull);
                g[2*i] = f.x; g[2*i+1] = f.y;
            }
            SORT8(g)
            #pragma unroll
            for (int i = 0; i < 8; i++) m[i] = fmaxf(m[i], g[7 - i]);
            BSORT8(m)
        }
        const float T = fmaxf(m[7], 0.05f);
        #pragma unroll
        for (int i = 0; i < NSTATES / 2; i++) {
            float2 f = unpack2(st2[i]);
            f.x = (fabsf(f.x) >= T) ? f.x : 0.0f;
            f.y = (fabsf(f.y) >= T) ? f.y : 0.0f;
            st2[i] = pack2(f.x, f.y);
        }
    }

    {
        ulonglong2* dst = reinterpret_cast<ulonglong2*>(sout) + (size_t)n * (NSTATES / 4);
        #pragma unroll
        for (int i = 0; i < NSTATES / 4; i++) {
            ulonglong2 v;
            v.x = st2[2*i+0];
            v.y = st2[2*i+1];
            dst[i] = v;
        }
    }
}

extern "C" void kernel_launch(void* const* d_in, const int* in_sizes, int n_in,
                              void* d_out, int out_size) {
    const float* x    = (const float*)d_in[0];
    const float* ns   = (const float*)d_in[1];
    const float* Wenc = (const float*)d_in[2];
    const float* benc = (const float*)d_in[3];
    const float* Wdec = (const float*)d_in[4];
    const float* bdec = (const float*)d_in[5];

    float* out  = (float*)d_out;
    float* xout = nullptr;
    float* sout = nullptr;
    if (out_size >= X_ELEMS + S_ELEMS) { xout = out; sout = out + X_ELEMS; }
    else if (out_size == S_ELEMS)      { sout = out; }
    else                               { xout = out; }

    const bool fork = g_fork.ok && xout && sout;

    if (fork) {
        // fork: tanh on side stream, states (+weight uploads) on main stream
        cudaEventRecord(g_fork.evFork, 0);
        cudaStreamWaitEvent(g_fork.s2, g_fork.evFork, 0);
        tanh_kernel<<<TANH_GRID, TTPB, 0, g_fork.s2>>>(
            reinterpret_cast<const float4*>(x), reinterpret_cast<float4*>(xout));
        cudaEventRecord(g_fork.evJoin, g_fork.s2);
    } else if (xout) {
        tanh_kernel<<<TANH_GRID, TTPB>>>(reinterpret_cast<const float4*>(x),
                                         reinterpret_cast<float4*>(xout));
    }

    if (sout) {
        cudaMemcpyToSymbolAsync(cWenc2, Wenc, CDIM * NSTATES * sizeof(float), 0,
                                cudaMemcpyDeviceToDevice);
        cudaMemcpyToSymbolAsync(cWdec2, Wdec, NSTATES * CDIM * sizeof(float), 0,
                                cudaMemcpyDeviceToDevice);
        states_kernel<<<N_NEURONS / STPB, STPB>>>(ns, benc, bdec, sout);
    }

    if (fork) cudaStreamWaitEvent(0, g_fork.evJoin, 0);
}